// round 15
// baseline (speedup 1.0000x reference)
#include <cuda_runtime.h>

// ContinuousPositionBias for GB300 — round 15:
// scatter: round-12 frozen. MLP: round-12 inner loop (unroll 2), reshaped to
// 256-thread blocks / flat indexing: 139 blocks x 8 warps = single wave,
// weight staging paid half as often, warps/SM unchanged.
// Inputs: 0 glob_pos(1,32,4) f32 | 1 coords_table(2209,2) f32 | 2 rpi(unused)
//         3 W1(2,512) | 4 b1(512) | 5 W2(512,16) | 6 num_prefix_tokens(=1)
// Output: (32,16,577,577) f32

#define NT     2209
#define HEADS  16
#define DHID   512
#define BATCH  32
#define OW     577
#define PLANE  (OW*OW)        // 332929
#define TOTT   (BATCH * NT)   // 70688

__device__ float g_bias[BATCH * HEADS * NT];   // (b,h,t)

typedef unsigned long long u64;

__device__ __forceinline__ u64 fma2(u64 a, u64 b, u64 c) {
    u64 d;
    asm("fma.rn.f32x2 %0, %1, %2, %3;" : "=l"(d) : "l"(a), "l"(b), "l"(c));
    return d;
}
__device__ __forceinline__ u64 pack2(float x) {
    u64 d;
    asm("mov.b64 %0, {%1, %1};" : "=l"(d) : "f"(x));
    return d;
}
__device__ __forceinline__ u64 packxy(float x, float y) {
    u64 d;
    asm("mov.b64 %0, {%1, %2};" : "=l"(d) : "f"(x), "f"(y));
    return d;
}
__device__ __forceinline__ void unpack2(u64 v, float& lo, float& hi) {
    asm("mov.b64 {%0, %1}, %2;" : "=f"(lo), "=f"(hi) : "l"(v));
}

// ---------------------------------------------------------------------------
// Kernel A: bias = relu((ctab+pos) @ W1 + b1) @ W2  (packed-h, 2t/thread,
// 256-thread blocks, flat (b,t) indexing)
// ---------------------------------------------------------------------------
__global__ __launch_bounds__(256) void mlp_kernel(
    const float* __restrict__ glob, const float* __restrict__ ctab,
    const float* __restrict__ W1,   const float* __restrict__ b1,
    const float* __restrict__ W2)
{
    __shared__ __align__(16) ulonglong2 w1a[DHID];      // (wx,wx | wy,wy)
    __shared__ __align__(16) u64        w1b[DHID];      // (wz,wz)
    __shared__ __align__(16) float      w2s[DHID * HEADS];

    const int tid = threadIdx.x;
    {
        const float4* src = (const float4*)W2;
        float4* dst = (float4*)w2s;
        #pragma unroll
        for (int k = tid; k < DHID * HEADS / 4; k += 256) dst[k] = src[k];
        for (int d = tid; d < DHID; d += 256) {
            const float wx = W1[d], wy = W1[DHID + d], wz = b1[d];
            ulonglong2 q;
            q.x = packxy(wx, wx);
            q.y = packxy(wy, wy);
            w1a[d] = q;
            w1b[d] = packxy(wz, wz);
        }
    }
    __syncthreads();

    int  bj[2], tj[2];
    bool vj[2];
    float c0j[2], c1j[2];

    #pragma unroll
    for (int j = 0; j < 2; j++) {
        const int flat = blockIdx.x * 512 + j * 256 + tid;
        vj[j] = (flat < TOTT);
        const int f = vj[j] ? flat : 0;
        const int b = f / NT;
        const int t = f - b * NT;
        const float g0 = glob[b*4+0], g1 = glob[b*4+1];
        const float g2 = glob[b*4+2], g3 = glob[b*4+3];
        float p0 = g2 / g0 * 8.0f;
        float p1 = g3 / g1 * 8.0f;
        p0 = copysignf(log2f(fabsf(p0) + 1.0f), p0) * (2.0f / 3.0f) - 1.0f;
        p1 = copysignf(log2f(fabsf(p1) + 1.0f), p1) * (2.0f / 3.0f) - 1.0f;
        bj[j]  = b; tj[j] = t;
        c0j[j] = ctab[2*t]   + p0;
        c1j[j] = ctab[2*t+1] + p1;
    }

    const u64 x01 = packxy(c0j[0], c0j[1]);
    const u64 y01 = packxy(c1j[0], c1j[1]);

    u64 accA[8], accB[8];
    #pragma unroll
    for (int k = 0; k < 8; k++) { accA[k] = 0ull; accB[k] = 0ull; }

    const ulonglong2* __restrict__ w2q = (const ulonglong2*)w2s;

    #pragma unroll 2
    for (int d = 0; d < DHID; d++) {
        const ulonglong2 wxy = w1a[d];
        const u64        wz2 = w1b[d];
        const u64 hp = fma2(x01, wxy.x, fma2(y01, wxy.y, wz2));
        float hAraw, hBraw;
        unpack2(hp, hAraw, hBraw);
        const u64 hA2 = pack2(fmaxf(hAraw, 0.0f));
        const u64 hB2 = pack2(fmaxf(hBraw, 0.0f));

        const ulonglong2 q0 = w2q[d*4 + 0];
        const ulonglong2 q1 = w2q[d*4 + 1];
        const ulonglong2 q2 = w2q[d*4 + 2];
        const ulonglong2 q3 = w2q[d*4 + 3];
        accA[0] = fma2(hA2, q0.x, accA[0]);  accB[0] = fma2(hB2, q0.x, accB[0]);
        accA[1] = fma2(hA2, q0.y, accA[1]);  accB[1] = fma2(hB2, q0.y, accB[1]);
        accA[2] = fma2(hA2, q1.x, accA[2]);  accB[2] = fma2(hB2, q1.x, accB[2]);
        accA[3] = fma2(hA2, q1.y, accA[3]);  accB[3] = fma2(hB2, q1.y, accB[3]);
        accA[4] = fma2(hA2, q2.x, accA[4]);  accB[4] = fma2(hB2, q2.x, accB[4]);
        accA[5] = fma2(hA2, q2.y, accA[5]);  accB[5] = fma2(hB2, q2.y, accB[5]);
        accA[6] = fma2(hA2, q3.x, accA[6]);  accB[6] = fma2(hB2, q3.x, accB[6]);
        accA[7] = fma2(hA2, q3.y, accA[7]);  accB[7] = fma2(hB2, q3.y, accB[7]);
    }

    if (vj[0]) {
        float* outb = g_bias + (size_t)bj[0] * (HEADS * NT) + tj[0];
        #pragma unroll
        for (int k = 0; k < 8; k++) {
            float lo, hi; unpack2(accA[k], lo, hi);
            outb[(2*k)   * NT] = lo;
            outb[(2*k+1) * NT] = hi;
        }
    }
    if (vj[1]) {
        float* outb = g_bias + (size_t)bj[1] * (HEADS * NT) + tj[1];
        #pragma unroll
        for (int k = 0; k < 8; k++) {
            float lo, hi; unpack2(accB[k], lo, hi);
            outb[(2*k)   * NT] = lo;
            outb[(2*k+1) * NT] = hi;
        }
    }
}

// ---------------------------------------------------------------------------
// Kernel B — diagonal-window scatter (round-12, frozen).
//   val(r=1+24ib+ii, c>=1) = rev[(23-ii) + f(c)],  f(c)=(c-1)+23*((c-1)/24)
// ---------------------------------------------------------------------------
#define FRONT 32

__global__ __launch_bounds__(192) void scatter_kernel(float* __restrict__ out)
{
    __shared__ float sh[1536];
    const int tid   = threadIdx.x;
    const int ib    = blockIdx.x;     // 0..23 bands, 24 = zero-row writer
    const int plane = blockIdx.y;     // 0..511
    float* __restrict__ pb = out + (size_t)plane * PLANE;

    if (ib == 24) {                   // row 0 is all zeros
        for (int c = tid; c < OW; c += 192) __stcs(pb + c, 0.0f);
        return;
    }

    const float* __restrict__ bp = g_bias + (size_t)plane * NT + 47 * ib;
    for (int u = tid; u < 1128; u += 192) {
        int a = (1127 - u) + FRONT;
        sh[a + (a >> 2)] = bp[u];
    }
    __syncthreads();

    const int w     = tid >> 5;
    const int lane  = tid & 31;
    const int ii0   = 4 * w;
    const int r0    = 1 + 24 * ib + ii0;
    const int basev = 23 - ii0;
    const int alpha = (int)(((size_t)plane * PLANE + (size_t)r0 * OW) & 3);
    const int cs    = (4 - alpha) & 3;
    float* __restrict__ rp = pb + (size_t)r0 * OW;

    for (int t = 0; t < 5; t++) {
        const int k = lane + 32 * t;
        if (k > 144) continue;
        const int cbase = cs + 4 * k;

        if (cbase >= 4 && cbase <= 573) {
            const int j0 = cbase - 1;
            const int q0 = (j0 * 2731) >> 16;
            const int m0 = j0 - 24 * q0;
            const int A  = basev + j0 + 23 * q0 + FRONT;

            float wv[10], wc5[5];
            {
                const int aW = A - 6;
                #pragma unroll
                for (int i = 0; i < 10; i++) { int a = aW + i; wv[i] = sh[a + (a >> 2)]; }
                const int aC = (m0 <= 2) ? (A - 29) : (A + 22);
                #pragma unroll
                for (int i = 0; i < 5; i++) { int a = aC + i; wc5[i] = sh[a + (a >> 2)]; }
            }

            #pragma unroll
            for (int di = 0; di < 4; di++) {
                float4 v;
                float* vv = (float*)&v;
                #pragma unroll
                for (int e = 0; e < 4; e++) {
                    const int x   = e - di;
                    const int idx = e - 2 * di + 6;
                    if (x > 0) {
                        vv[e] = (m0 >= 24 - x) ? wc5[idx - 5] : wv[idx];
                    } else if (x < 0) {
                        vv[e] = (m0 <  -x)     ? wc5[idx]     : wv[idx];
                    } else {
                        vv[e] = wv[idx];
                    }
                }
                __stcs((float4*)(rp + di * OW + (cbase - di)), v);
            }
        } else {
            #pragma unroll
            for (int di = 0; di < 4; di++) {
                int clo = (k == 0) ? 0 : (cbase - di);
                int chi = cbase - di + 3;
                if (chi > 576) chi = 576;
                for (int c = clo; c <= chi; c++) {
                    float val = 0.0f;
                    if (c >= 1) {
                        const int j = c - 1;
                        const int q = (j * 2731) >> 16;
                        const int a = basev - di + j + 23 * q + FRONT;
                        val = sh[a + (a >> 2)];
                    }
                    __stcs(rp + di * OW + c, val);
                }
            }
        }
    }
}

// ---------------------------------------------------------------------------
extern "C" void kernel_launch(void* const* d_in, const int* in_sizes, int n_in,
                              void* d_out, int out_size)
{
    const float* glob = (const float*)d_in[0];
    const float* ctab = (const float*)d_in[1];
    const float* W1   = (const float*)d_in[3];
    const float* b1   = (const float*)d_in[4];
    const float* W2   = (const float*)d_in[5];
    float* out        = (float*)d_out;

    mlp_kernel<<<dim3((TOTT + 511) / 512), 256>>>(glob, ctab, W1, b1, W2);
    scatter_kernel<<<dim3(25, BATCH * HEADS), 192>>>(out);
}

// round 16
// speedup vs baseline: 1.0542x; 1.0542x over previous
#include <cuda_runtime.h>

// ContinuousPositionBias for GB300 — FINAL (round-12 champion, 143.2us):
//  * MLP: packed-h f32x2 dual-t pipeline, 128thr x (9,32) grid, unroll 2.
//  * Scatter: analytic-rpi diagonal-window gather, 4x4 tiles, STG.128
//    streaming stores; ~6 TB/s effective write bandwidth (roofline).
// Inputs: 0 glob_pos(1,32,4) f32 | 1 coords_table(2209,2) f32 | 2 rpi(unused)
//         3 W1(2,512) | 4 b1(512) | 5 W2(512,16) | 6 num_prefix_tokens(=1)
// Output: (32,16,577,577) f32

#define NT     2209
#define HEADS  16
#define DHID   512
#define BATCH  32
#define OW     577
#define PLANE  (OW*OW)    // 332929

__device__ float g_bias[BATCH * HEADS * NT];   // (b,h,t)

typedef unsigned long long u64;

__device__ __forceinline__ u64 fma2(u64 a, u64 b, u64 c) {
    u64 d;
    asm("fma.rn.f32x2 %0, %1, %2, %3;" : "=l"(d) : "l"(a), "l"(b), "l"(c));
    return d;
}
__device__ __forceinline__ u64 pack2(float x) {
    u64 d;
    asm("mov.b64 %0, {%1, %1};" : "=l"(d) : "f"(x));
    return d;
}
__device__ __forceinline__ u64 packxy(float x, float y) {
    u64 d;
    asm("mov.b64 %0, {%1, %2};" : "=l"(d) : "f"(x), "f"(y));
    return d;
}
__device__ __forceinline__ void unpack2(u64 v, float& lo, float& hi) {
    asm("mov.b64 {%0, %1}, %2;" : "=f"(lo), "=f"(hi) : "l"(v));
}

// ---------------------------------------------------------------------------
// Kernel A: bias = relu((ctab+pos) @ W1 + b1) @ W2  (packed-h, 2t/thread)
// ---------------------------------------------------------------------------
__global__ __launch_bounds__(128) void mlp_kernel(
    const float* __restrict__ glob, const float* __restrict__ ctab,
    const float* __restrict__ W1,   const float* __restrict__ b1,
    const float* __restrict__ W2)
{
    __shared__ __align__(16) ulonglong2 w1a[DHID];      // (wx,wx | wy,wy)
    __shared__ __align__(16) u64        w1b[DHID];      // (wz,wz)
    __shared__ __align__(16) float      w2s[DHID * HEADS];

    const int tid = threadIdx.x;
    {
        const float4* src = (const float4*)W2;
        float4* dst = (float4*)w2s;
        #pragma unroll
        for (int k = tid; k < DHID * HEADS / 4; k += 128) dst[k] = src[k];
        for (int d = tid; d < DHID; d += 128) {
            const float wx = W1[d], wy = W1[DHID + d], wz = b1[d];
            ulonglong2 q;
            q.x = packxy(wx, wx);
            q.y = packxy(wy, wy);
            w1a[d] = q;
            w1b[d] = packxy(wz, wz);
        }
    }
    __syncthreads();

    const int b = blockIdx.y;
    const float g0 = glob[b*4+0], g1 = glob[b*4+1];
    const float g2 = glob[b*4+2], g3 = glob[b*4+3];
    float p0 = g2 / g0 * 8.0f;
    float p1 = g3 / g1 * 8.0f;
    p0 = copysignf(log2f(fabsf(p0) + 1.0f), p0) * (2.0f / 3.0f) - 1.0f;
    p1 = copysignf(log2f(fabsf(p1) + 1.0f), p1) * (2.0f / 3.0f) - 1.0f;

    const int t0 = blockIdx.x * 256 + tid;
    const int t1 = t0 + 128;
    const bool v0 = (t0 < NT), v1 = (t1 < NT);

    float a0 = 0.f, a1 = 0.f, c0 = 0.f, c1 = 0.f;
    if (v0) { a0 = ctab[2*t0] + p0; a1 = ctab[2*t0+1] + p1; }
    if (v1) { c0 = ctab[2*t1] + p0; c1 = ctab[2*t1+1] + p1; }

    const u64 x01 = packxy(a0, c0);
    const u64 y01 = packxy(a1, c1);

    u64 accA[8], accB[8];
    #pragma unroll
    for (int k = 0; k < 8; k++) { accA[k] = 0ull; accB[k] = 0ull; }

    const ulonglong2* __restrict__ w2q = (const ulonglong2*)w2s;

    #pragma unroll 2
    for (int d = 0; d < DHID; d++) {
        const ulonglong2 wxy = w1a[d];
        const u64        wz2 = w1b[d];
        const u64 hp = fma2(x01, wxy.x, fma2(y01, wxy.y, wz2));
        float hAraw, hBraw;
        unpack2(hp, hAraw, hBraw);
        const u64 hA2 = pack2(fmaxf(hAraw, 0.0f));
        const u64 hB2 = pack2(fmaxf(hBraw, 0.0f));

        const ulonglong2 q0 = w2q[d*4 + 0];
        const ulonglong2 q1 = w2q[d*4 + 1];
        const ulonglong2 q2 = w2q[d*4 + 2];
        const ulonglong2 q3 = w2q[d*4 + 3];
        accA[0] = fma2(hA2, q0.x, accA[0]);  accB[0] = fma2(hB2, q0.x, accB[0]);
        accA[1] = fma2(hA2, q0.y, accA[1]);  accB[1] = fma2(hB2, q0.y, accB[1]);
        accA[2] = fma2(hA2, q1.x, accA[2]);  accB[2] = fma2(hB2, q1.x, accB[2]);
        accA[3] = fma2(hA2, q1.y, accA[3]);  accB[3] = fma2(hB2, q1.y, accB[3]);
        accA[4] = fma2(hA2, q2.x, accA[4]);  accB[4] = fma2(hB2, q2.x, accB[4]);
        accA[5] = fma2(hA2, q2.y, accA[5]);  accB[5] = fma2(hB2, q2.y, accB[5]);
        accA[6] = fma2(hA2, q3.x, accA[6]);  accB[6] = fma2(hB2, q3.x, accB[6]);
        accA[7] = fma2(hA2, q3.y, accA[7]);  accB[7] = fma2(hB2, q3.y, accB[7]);
    }

    float* base = g_bias + (size_t)b * (HEADS * NT);
    if (v0) {
        #pragma unroll
        for (int k = 0; k < 8; k++) {
            float lo, hi; unpack2(accA[k], lo, hi);
            base[(2*k)   * NT + t0] = lo;
            base[(2*k+1) * NT + t0] = hi;
        }
    }
    if (v1) {
        #pragma unroll
        for (int k = 0; k < 8; k++) {
            float lo, hi; unpack2(accB[k], lo, hi);
            base[(2*k)   * NT + t1] = lo;
            base[(2*k+1) * NT + t1] = hi;
        }
    }
}

// ---------------------------------------------------------------------------
// Kernel B — diagonal-window scatter.
//   val(r=1+24ib+ii, c>=1) = rev[(23-ii) + f(c)],  f(c)=(c-1)+23*((c-1)/24)
// Main window wv[10] at A-6; crossing window wc5[5] at (m0<=2 ? A-29 : A+22).
// ---------------------------------------------------------------------------
#define FRONT 32

__global__ __launch_bounds__(192) void scatter_kernel(float* __restrict__ out)
{
    __shared__ float sh[1536];
    const int tid   = threadIdx.x;
    const int ib    = blockIdx.x;     // 0..23 bands, 24 = zero-row writer
    const int plane = blockIdx.y;     // 0..511
    float* __restrict__ pb = out + (size_t)plane * PLANE;

    if (ib == 24) {                   // row 0 is all zeros
        for (int c = tid; c < OW; c += 192) __stcs(pb + c, 0.0f);
        return;
    }

    const float* __restrict__ bp = g_bias + (size_t)plane * NT + 47 * ib;
    for (int u = tid; u < 1128; u += 192) {
        int a = (1127 - u) + FRONT;
        sh[a + (a >> 2)] = bp[u];
    }
    __syncthreads();

    const int w     = tid >> 5;
    const int lane  = tid & 31;
    const int ii0   = 4 * w;
    const int r0    = 1 + 24 * ib + ii0;
    const int basev = 23 - ii0;
    const int alpha = (int)(((size_t)plane * PLANE + (size_t)r0 * OW) & 3);
    const int cs    = (4 - alpha) & 3;
    float* __restrict__ rp = pb + (size_t)r0 * OW;

    for (int t = 0; t < 5; t++) {
        const int k = lane + 32 * t;
        if (k > 144) continue;
        const int cbase = cs + 4 * k;

        if (cbase >= 4 && cbase <= 573) {
            const int j0 = cbase - 1;
            const int q0 = (j0 * 2731) >> 16;
            const int m0 = j0 - 24 * q0;
            const int A  = basev + j0 + 23 * q0 + FRONT;

            float wv[10], wc5[5];
            {
                const int aW = A - 6;
                #pragma unroll
                for (int i = 0; i < 10; i++) { int a = aW + i; wv[i] = sh[a + (a >> 2)]; }
                const int aC = (m0 <= 2) ? (A - 29) : (A + 22);
                #pragma unroll
                for (int i = 0; i < 5; i++) { int a = aC + i; wc5[i] = sh[a + (a >> 2)]; }
            }

            #pragma unroll
            for (int di = 0; di < 4; di++) {
                float4 v;
                float* vv = (float*)&v;
                #pragma unroll
                for (int e = 0; e < 4; e++) {
                    const int x   = e - di;
                    const int idx = e - 2 * di + 6;
                    if (x > 0) {
                        vv[e] = (m0 >= 24 - x) ? wc5[idx - 5] : wv[idx];
                    } else if (x < 0) {
                        vv[e] = (m0 <  -x)     ? wc5[idx]     : wv[idx];
                    } else {
                        vv[e] = wv[idx];
                    }
                }
                __stcs((float4*)(rp + di * OW + (cbase - di)), v);
            }
        } else {
            #pragma unroll
            for (int di = 0; di < 4; di++) {
                int clo = (k == 0) ? 0 : (cbase - di);
                int chi = cbase - di + 3;
                if (chi > 576) chi = 576;
                for (int c = clo; c <= chi; c++) {
                    float val = 0.0f;
                    if (c >= 1) {
                        const int j = c - 1;
                        const int q = (j * 2731) >> 16;
                        const int a = basev - di + j + 23 * q + FRONT;
                        val = sh[a + (a >> 2)];
                    }
                    __stcs(rp + di * OW + c, val);
                }
            }
        }
    }
}

// ---------------------------------------------------------------------------
extern "C" void kernel_launch(void* const* d_in, const int* in_sizes, int n_in,
                              void* d_out, int out_size)
{
    const float* glob = (const float*)d_in[0];
    const float* ctab = (const float*)d_in[1];
    const float* W1   = (const float*)d_in[3];
    const float* b1   = (const float*)d_in[4];
    const float* W2   = (const float*)d_in[5];
    float* out        = (float*)d_out;

    mlp_kernel<<<dim3((NT + 255) / 256, BATCH), 128>>>(glob, ctab, W1, b1, W2);
    scatter_kernel<<<dim3(25, BATCH * HEADS), 192>>>(out);
}

// round 17
// speedup vs baseline: 1.0587x; 1.0042x over previous
#include <cuda_runtime.h>

// ContinuousPositionBias for GB300 — FINAL champion (143.2us best, re-validated 144.0us):
//  * MLP (~30us): packed-h f32x2 dual-t pipeline, 128thr x (9,32) grid, unroll 2.
//    Hidden activations for both t computed in ONE f32x2 chain off pre-duplicated
//    smem weights; 16 head-accumulators as 8 f32x2 per t.
//  * Scatter (~113us, HBM write roofline): analytic rpi (zero index memory),
//    reversed+padded smem staging, diagonal-window gather (10+5-word register
//    windows, static selects), 4x4 tiles, aligned STG.128 streaming stores.
// Inputs: 0 glob_pos(1,32,4) f32 | 1 coords_table(2209,2) f32 | 2 rpi(unused)
//         3 W1(2,512) | 4 b1(512) | 5 W2(512,16) | 6 num_prefix_tokens(=1)
// Output: (32,16,577,577) f32

#define NT     2209
#define HEADS  16
#define DHID   512
#define BATCH  32
#define OW     577
#define PLANE  (OW*OW)    // 332929

__device__ float g_bias[BATCH * HEADS * NT];   // (b,h,t)

typedef unsigned long long u64;

__device__ __forceinline__ u64 fma2(u64 a, u64 b, u64 c) {
    u64 d;
    asm("fma.rn.f32x2 %0, %1, %2, %3;" : "=l"(d) : "l"(a), "l"(b), "l"(c));
    return d;
}
__device__ __forceinline__ u64 pack2(float x) {
    u64 d;
    asm("mov.b64 %0, {%1, %1};" : "=l"(d) : "f"(x));
    return d;
}
__device__ __forceinline__ u64 packxy(float x, float y) {
    u64 d;
    asm("mov.b64 %0, {%1, %2};" : "=l"(d) : "f"(x), "f"(y));
    return d;
}
__device__ __forceinline__ void unpack2(u64 v, float& lo, float& hi) {
    asm("mov.b64 {%0, %1}, %2;" : "=f"(lo), "=f"(hi) : "l"(v));
}

// ---------------------------------------------------------------------------
// Kernel A: bias = relu((ctab+pos) @ W1 + b1) @ W2  (packed-h, 2t/thread)
// ---------------------------------------------------------------------------
__global__ __launch_bounds__(128) void mlp_kernel(
    const float* __restrict__ glob, const float* __restrict__ ctab,
    const float* __restrict__ W1,   const float* __restrict__ b1,
    const float* __restrict__ W2)
{
    __shared__ __align__(16) ulonglong2 w1a[DHID];      // (wx,wx | wy,wy)
    __shared__ __align__(16) u64        w1b[DHID];      // (wz,wz)
    __shared__ __align__(16) float      w2s[DHID * HEADS];

    const int tid = threadIdx.x;
    {
        const float4* src = (const float4*)W2;
        float4* dst = (float4*)w2s;
        #pragma unroll
        for (int k = tid; k < DHID * HEADS / 4; k += 128) dst[k] = src[k];
        for (int d = tid; d < DHID; d += 128) {
            const float wx = W1[d], wy = W1[DHID + d], wz = b1[d];
            ulonglong2 q;
            q.x = packxy(wx, wx);
            q.y = packxy(wy, wy);
            w1a[d] = q;
            w1b[d] = packxy(wz, wz);
        }
    }
    __syncthreads();

    const int b = blockIdx.y;
    const float g0 = glob[b*4+0], g1 = glob[b*4+1];
    const float g2 = glob[b*4+2], g3 = glob[b*4+3];
    float p0 = g2 / g0 * 8.0f;
    float p1 = g3 / g1 * 8.0f;
    p0 = copysignf(log2f(fabsf(p0) + 1.0f), p0) * (2.0f / 3.0f) - 1.0f;
    p1 = copysignf(log2f(fabsf(p1) + 1.0f), p1) * (2.0f / 3.0f) - 1.0f;

    const int t0 = blockIdx.x * 256 + tid;
    const int t1 = t0 + 128;
    const bool v0 = (t0 < NT), v1 = (t1 < NT);

    float a0 = 0.f, a1 = 0.f, c0 = 0.f, c1 = 0.f;
    if (v0) { a0 = ctab[2*t0] + p0; a1 = ctab[2*t0+1] + p1; }
    if (v1) { c0 = ctab[2*t1] + p0; c1 = ctab[2*t1+1] + p1; }

    const u64 x01 = packxy(a0, c0);
    const u64 y01 = packxy(a1, c1);

    u64 accA[8], accB[8];
    #pragma unroll
    for (int k = 0; k < 8; k++) { accA[k] = 0ull; accB[k] = 0ull; }

    const ulonglong2* __restrict__ w2q = (const ulonglong2*)w2s;

    #pragma unroll 2
    for (int d = 0; d < DHID; d++) {
        const ulonglong2 wxy = w1a[d];
        const u64        wz2 = w1b[d];
        const u64 hp = fma2(x01, wxy.x, fma2(y01, wxy.y, wz2));
        float hAraw, hBraw;
        unpack2(hp, hAraw, hBraw);
        const u64 hA2 = pack2(fmaxf(hAraw, 0.0f));
        const u64 hB2 = pack2(fmaxf(hBraw, 0.0f));

        const ulonglong2 q0 = w2q[d*4 + 0];
        const ulonglong2 q1 = w2q[d*4 + 1];
        const ulonglong2 q2 = w2q[d*4 + 2];
        const ulonglong2 q3 = w2q[d*4 + 3];
        accA[0] = fma2(hA2, q0.x, accA[0]);  accB[0] = fma2(hB2, q0.x, accB[0]);
        accA[1] = fma2(hA2, q0.y, accA[1]);  accB[1] = fma2(hB2, q0.y, accB[1]);
        accA[2] = fma2(hA2, q1.x, accA[2]);  accB[2] = fma2(hB2, q1.x, accB[2]);
        accA[3] = fma2(hA2, q1.y, accA[3]);  accB[3] = fma2(hB2, q1.y, accB[3]);
        accA[4] = fma2(hA2, q2.x, accA[4]);  accB[4] = fma2(hB2, q2.x, accB[4]);
        accA[5] = fma2(hA2, q2.y, accA[5]);  accB[5] = fma2(hB2, q2.y, accB[5]);
        accA[6] = fma2(hA2, q3.x, accA[6]);  accB[6] = fma2(hB2, q3.x, accB[6]);
        accA[7] = fma2(hA2, q3.y, accA[7]);  accB[7] = fma2(hB2, q3.y, accB[7]);
    }

    float* base = g_bias + (size_t)b * (HEADS * NT);
    if (v0) {
        #pragma unroll
        for (int k = 0; k < 8; k++) {
            float lo, hi; unpack2(accA[k], lo, hi);
            base[(2*k)   * NT + t0] = lo;
            base[(2*k+1) * NT + t0] = hi;
        }
    }
    if (v1) {
        #pragma unroll
        for (int k = 0; k < 8; k++) {
            float lo, hi; unpack2(accB[k], lo, hi);
            base[(2*k)   * NT + t1] = lo;
            base[(2*k+1) * NT + t1] = hi;
        }
    }
}

// ---------------------------------------------------------------------------
// Kernel B — diagonal-window scatter.
//   val(r=1+24ib+ii, c>=1) = rev[(23-ii) + f(c)],  f(c)=(c-1)+23*((c-1)/24)
// Main window wv[10] at A-6; crossing window wc5[5] at (m0<=2 ? A-29 : A+22).
// ---------------------------------------------------------------------------
#define FRONT 32

__global__ __launch_bounds__(192) void scatter_kernel(float* __restrict__ out)
{
    __shared__ float sh[1536];
    const int tid   = threadIdx.x;
    const int ib    = blockIdx.x;     // 0..23 bands, 24 = zero-row writer
    const int plane = blockIdx.y;     // 0..511
    float* __restrict__ pb = out + (size_t)plane * PLANE;

    if (ib == 24) {                   // row 0 is all zeros
        for (int c = tid; c < OW; c += 192) __stcs(pb + c, 0.0f);
        return;
    }

    const float* __restrict__ bp = g_bias + (size_t)plane * NT + 47 * ib;
    for (int u = tid; u < 1128; u += 192) {
        int a = (1127 - u) + FRONT;
        sh[a + (a >> 2)] = bp[u];
    }
    __syncthreads();

    const int w     = tid >> 5;
    const int lane  = tid & 31;
    const int ii0   = 4 * w;
    const int r0    = 1 + 24 * ib + ii0;
    const int basev = 23 - ii0;
    const int alpha = (int)(((size_t)plane * PLANE + (size_t)r0 * OW) & 3);
    const int cs    = (4 - alpha) & 3;
    float* __restrict__ rp = pb + (size_t)r0 * OW;

    for (int t = 0; t < 5; t++) {
        const int k = lane + 32 * t;
        if (k > 144) continue;
        const int cbase = cs + 4 * k;

        if (cbase >= 4 && cbase <= 573) {
            const int j0 = cbase - 1;
            const int q0 = (j0 * 2731) >> 16;
            const int m0 = j0 - 24 * q0;
            const int A  = basev + j0 + 23 * q0 + FRONT;

            float wv[10], wc5[5];
            {
                const int aW = A - 6;
                #pragma unroll
                for (int i = 0; i < 10; i++) { int a = aW + i; wv[i] = sh[a + (a >> 2)]; }
                const int aC = (m0 <= 2) ? (A - 29) : (A + 22);
                #pragma unroll
                for (int i = 0; i < 5; i++) { int a = aC + i; wc5[i] = sh[a + (a >> 2)]; }
            }

            #pragma unroll
            for (int di = 0; di < 4; di++) {
                float4 v;
                float* vv = (float*)&v;
                #pragma unroll
                for (int e = 0; e < 4; e++) {
                    const int x   = e - di;
                    const int idx = e - 2 * di + 6;
                    if (x > 0) {
                        vv[e] = (m0 >= 24 - x) ? wc5[idx - 5] : wv[idx];
                    } else if (x < 0) {
                        vv[e] = (m0 <  -x)     ? wc5[idx]     : wv[idx];
                    } else {
                        vv[e] = wv[idx];
                    }
                }
                __stcs((float4*)(rp + di * OW + (cbase - di)), v);
            }
        } else {
            #pragma unroll
            for (int di = 0; di < 4; di++) {
                int clo = (k == 0) ? 0 : (cbase - di);
                int chi = cbase - di + 3;
                if (chi > 576) chi = 576;
                for (int c = clo; c <= chi; c++) {
                    float val = 0.0f;
                    if (c >= 1) {
                        const int j = c - 1;
                        const int q = (j * 2731) >> 16;
                        const int a = basev - di + j + 23 * q + FRONT;
                        val = sh[a + (a >> 2)];
                    }
                    __stcs(rp + di * OW + c, val);
                }
            }
        }
    }
}

// ---------------------------------------------------------------------------
extern "C" void kernel_launch(void* const* d_in, const int* in_sizes, int n_in,
                              void* d_out, int out_size)
{
    const float* glob = (const float*)d_in[0];
    const float* ctab = (const float*)d_in[1];
    const float* W1   = (const float*)d_in[3];
    const float* b1   = (const float*)d_in[4];
    const float* W2   = (const float*)d_in[5];
    float* out        = (float*)d_out;

    mlp_kernel<<<dim3((NT + 255) / 256, BATCH), 128>>>(glob, ctab, W1, b1, W2);
    scatter_kernel<<<dim3(25, BATCH * HEADS), 192>>>(out);
}